// round 8
// baseline (speedup 1.0000x reference)
#include <cuda_runtime.h>
#include <cuda_bf16.h>
#include <cuda_fp16.h>
#include <math.h>
#include <cstdint>

#define NN 100000
#define HID 128
#define NE 1600000
#define NC 10
#define HALF0 50048                 // = 391*128 = 6256*8
#define HALF1 (NN - HALF0)          // 49952

// ---------------- scratch (device globals; no allocation allowed) -------------
__device__ int    g_cnt[NN];
__device__ int    g_rowptr[NN];
__device__ int    g_col[NE];
__device__ int    g_pos[NE];                   // intra-segment position per edge
__device__ int    g_blockSums[256];
__device__ __half g_bufH1[(size_t)NN * HID];   // layer-1 h' = invs*h (fp16)
__device__ __half g_bufH2[(size_t)NN * HID];   // layer-2 h' (fp16)
__device__ __half g_bufX[(size_t)NN * HID];    // layer-1 activation x (fp16)
// bf16 hi/lo weight images, layout [n][k/2] u32 pairs
__device__ uint32_t g_W1hi[128 * 64];
__device__ uint32_t g_W1lo[128 * 64];
__device__ uint32_t g_W2hi[128 * 64];
__device__ uint32_t g_W2lo[128 * 64];

// ---------------- degree histogram + position record (single atomic pass) ----
__global__ void k_count(const int* __restrict__ dst) {
    int e4 = blockIdx.x * blockDim.x + threadIdx.x;
    if (e4 < NE / 4) {
        int4 d = ((const int4*)dst)[e4];
        int4 p;
        p.x = atomicAdd(&g_cnt[d.x], 1);
        p.y = atomicAdd(&g_cnt[d.y], 1);
        p.z = atomicAdd(&g_cnt[d.z], 1);
        p.w = atomicAdd(&g_cnt[d.w], 1);
        ((int4*)g_pos)[e4] = p;
    }
}

// ---------------- exclusive scan (3-phase) ----------------
__global__ void k_scanA() {
    __shared__ int s[512];
    int i = blockIdx.x * 512 + threadIdx.x;
    int v = (i < NN) ? g_cnt[i] : 0;
    s[threadIdx.x] = v;
    __syncthreads();
    #pragma unroll
    for (int off = 1; off < 512; off <<= 1) {
        int t = (threadIdx.x >= off) ? s[threadIdx.x - off] : 0;
        __syncthreads();
        s[threadIdx.x] += t;
        __syncthreads();
    }
    if (i < NN) g_rowptr[i] = s[threadIdx.x] - v;        // exclusive
    if (threadIdx.x == 511) g_blockSums[blockIdx.x] = s[511];
}

__global__ void k_scanB(int nblocks) {
    __shared__ int s[256];
    int t = threadIdx.x;
    int v = (t < nblocks) ? g_blockSums[t] : 0;
    s[t] = v;
    __syncthreads();
    #pragma unroll
    for (int off = 1; off < 256; off <<= 1) {
        int u = (t >= off) ? s[t - off] : 0;
        __syncthreads();
        s[t] += u;
        __syncthreads();
    }
    if (t < nblocks) g_blockSums[t] = s[t] - v;           // exclusive
}

__global__ void k_scanC() {
    int i = blockIdx.x * 512 + threadIdx.x;
    if (i < NN) g_rowptr[i] += g_blockSums[blockIdx.x];
}

// ---------------- CSR place (no atomics) ----------------
__global__ void k_place(const int* __restrict__ src, const int* __restrict__ dst) {
    int e4 = blockIdx.x * blockDim.x + threadIdx.x;
    if (e4 < NE / 4) {
        int4 s = ((const int4*)src)[e4];
        int4 d = ((const int4*)dst)[e4];
        int4 p = ((const int4*)g_pos)[e4];
        g_col[g_rowptr[d.x] + p.x] = s.x;
        g_col[g_rowptr[d.y] + p.y] = s.y;
        g_col[g_rowptr[d.z] + p.z] = s.z;
        g_col[g_rowptr[d.w] + p.w] = s.w;
    }
}

// ---------------- weight image precompute ----------------
__global__ void k_wimg(const float* __restrict__ W, int layer) {
    uint32_t* hiImg = (layer == 0 ? g_W1hi : g_W2hi);
    uint32_t* loImg = (layer == 0 ? g_W1lo : g_W2lo);
    int idx = blockIdx.x * blockDim.x + threadIdx.x;      // 0..8191 (pairs)
    if (idx >= 128 * 64) return;
    int n = idx >> 6, cp = idx & 63;
    int k0 = 2 * cp;
    float w0 = W[(size_t)k0 * HID + n];
    float w1 = W[(size_t)(k0 + 1) * HID + n];
    __nv_bfloat16 h0 = __float2bfloat16(w0), h1 = __float2bfloat16(w1);
    __nv_bfloat16 l0 = __float2bfloat16(w0 - __bfloat162float(h0));
    __nv_bfloat16 l1 = __float2bfloat16(w1 - __bfloat162float(h1));
    hiImg[idx] = (uint32_t)__bfloat16_as_ushort(h0) | ((uint32_t)__bfloat16_as_ushort(h1) << 16);
    loImg[idx] = (uint32_t)__bfloat16_as_ushort(l0) | ((uint32_t)__bfloat16_as_ushort(l1) << 16);
}

// ---------------- mma.sync bf16x3 GEMM -> fp16 pre-scaled output -------------
// h'[r][:] = rsqrt(cnt[r]+1) * (A[r][:] @ W), stored fp16.
// layer 0: reads fp32 Af32, writes g_bufH1. layer 1: reads g_bufX, writes g_bufH2.
#define ROWW 68
#define MAT_W (128 * ROWW)
#define DSMEM_SZ (4 * MAT_W * 4)

__device__ __forceinline__ void mma_bf16(float* d, uint32_t a0, uint32_t a1,
                                         uint32_t a2, uint32_t a3,
                                         uint32_t b0, uint32_t b1) {
    asm volatile(
        "mma.sync.aligned.m16n8k16.row.col.f32.bf16.bf16.f32 "
        "{%0,%1,%2,%3}, {%4,%5,%6,%7}, {%8,%9}, {%0,%1,%2,%3};\n"
        : "+f"(d[0]), "+f"(d[1]), "+f"(d[2]), "+f"(d[3])
        : "r"(a0), "r"(a1), "r"(a2), "r"(a3), "r"(b0), "r"(b1));
}

__global__ void __launch_bounds__(256, 1) k_gemm_mma(const float* Af32, int layer, int rowBase) {
    extern __shared__ uint32_t sm[];
    uint32_t* sAhi = sm;
    uint32_t* sAlo = sm + MAT_W;
    uint32_t* sWhi = sm + 2 * MAT_W;
    uint32_t* sWlo = sm + 3 * MAT_W;

    const uint32_t* whi = (layer == 0 ? g_W1hi : g_W2hi);
    const uint32_t* wlo = (layer == 0 ? g_W1lo : g_W2lo);
    __half* outH = (layer == 0 ? g_bufH1 : g_bufH2);

    int tid = threadIdx.x;
    int wid = tid >> 5, lane = tid & 31;
    int g = lane >> 2, t = lane & 3;
    int blockRow = rowBase + blockIdx.x * 128;

    // Stage W images
    #pragma unroll
    for (int i = 0; i < 32; i++) {
        int idx = tid + i * 256;
        int row = idx >> 6, c = idx & 63;
        sWhi[row * ROWW + c] = whi[idx];
        sWlo[row * ROWW + c] = wlo[idx];
    }

    // Convert A tile (fp32 input or fp16 g_bufX) -> bf16 hi/lo
    #pragma unroll
    for (int i = 0; i < 32; i++) {
        int idx = tid + i * 256;
        int row = idx >> 6, c = idx & 63;
        int gr = blockRow + row;
        float2 v = make_float2(0.f, 0.f);
        if (gr < NN) {
            if (Af32) {
                v = *(const float2*)&Af32[(size_t)gr * HID + 2 * c];
            } else {
                uint32_t u = ((const uint32_t*)(g_bufX + (size_t)gr * HID))[c];
                v = __half22float2(*(const __half2*)&u);
            }
        }
        __nv_bfloat16 h0 = __float2bfloat16(v.x), h1 = __float2bfloat16(v.y);
        __nv_bfloat16 l0 = __float2bfloat16(v.x - __bfloat162float(h0));
        __nv_bfloat16 l1 = __float2bfloat16(v.y - __bfloat162float(h1));
        sAhi[row * ROWW + c] = (uint32_t)__bfloat16_as_ushort(h0) | ((uint32_t)__bfloat16_as_ushort(h1) << 16);
        sAlo[row * ROWW + c] = (uint32_t)__bfloat16_as_ushort(l0) | ((uint32_t)__bfloat16_as_ushort(l1) << 16);
    }
    __syncthreads();

    float acc[16][4];
    #pragma unroll
    for (int j = 0; j < 16; j++)
        #pragma unroll
        for (int q = 0; q < 4; q++) acc[j][q] = 0.f;

    int rowA0 = (wid * 16 + g) * ROWW;
    int rowA1 = rowA0 + 8 * ROWW;

    #pragma unroll
    for (int kc = 0; kc < 8; kc++) {
        int kw = kc * 8 + t;
        uint32_t ah0 = sAhi[rowA0 + kw], ah1 = sAhi[rowA1 + kw];
        uint32_t ah2 = sAhi[rowA0 + kw + 4], ah3 = sAhi[rowA1 + kw + 4];
        uint32_t al0 = sAlo[rowA0 + kw], al1 = sAlo[rowA1 + kw];
        uint32_t al2 = sAlo[rowA0 + kw + 4], al3 = sAlo[rowA1 + kw + 4];
        #pragma unroll
        for (int j = 0; j < 16; j++) {
            int rb = (j * 8 + g) * ROWW + kw;
            uint32_t bh0 = sWhi[rb], bh1 = sWhi[rb + 4];
            uint32_t bl0 = sWlo[rb], bl1 = sWlo[rb + 4];
            mma_bf16(acc[j], ah0, ah1, ah2, ah3, bh0, bh1);
            mma_bf16(acc[j], al0, al1, al2, al3, bh0, bh1);
            mma_bf16(acc[j], ah0, ah1, ah2, ah3, bl0, bl1);
        }
    }

    // Epilogue: scale by rsqrt(cnt+1) computed inline, store fp16 h'
    int gr0 = blockRow + wid * 16 + g;
    int gr1 = gr0 + 8;
    float wn0 = (gr0 < NN) ? rsqrtf((float)(g_cnt[gr0] + 1)) : 0.f;
    float wn1 = (gr1 < NN) ? rsqrtf((float)(g_cnt[gr1] + 1)) : 0.f;
    #pragma unroll
    for (int j = 0; j < 16; j++) {
        int col = j * 8 + 2 * t;
        if (gr0 < NN)
            *(__half2*)&outH[(size_t)gr0 * HID + col] =
                __floats2half2_rn(wn0 * acc[j][0], wn0 * acc[j][1]);
        if (gr1 < NN)
            *(__half2*)&outH[(size_t)gr1 * HID + col] =
                __floats2half2_rn(wn1 * acc[j][2], wn1 * acc[j][3]);
    }
}

// ---------------- gather-aggregate + bias + relu (+ fused output proj) -------
// agg[n] = rsqrt(cnt[n]+1) * sum_{s in N(n) U {n}} h'[s];  x = relu(agg + b)
__global__ void k_agg(int layer, int nodeBase, const float* __restrict__ bias,
                      const float* __restrict__ Wout, const float* __restrict__ bout,
                      float* __restrict__ out) {
    const __half* h = (layer == 0 ? g_bufH1 : g_bufH2);
    __shared__ float Ws[HID * NC];
    __shared__ float bs[NC];

    int tid = threadIdx.x;
    if (Wout) {
        for (int i = tid; i < HID * NC; i += blockDim.x) Ws[i] = Wout[i];
        if (tid < NC) bs[tid] = bout[tid];
        __syncthreads();
    }

    int n = nodeBase + ((blockIdx.x * blockDim.x + tid) >> 5);
    int lane = tid & 31;

    float ax, ay, az, aw;
    {
        uint2 v = ((const uint2*)(h + (size_t)n * HID))[lane];
        float2 p0 = __half22float2(*(const __half2*)&v.x);
        float2 p1 = __half22float2(*(const __half2*)&v.y);
        ax = p0.x; ay = p0.y; az = p1.x; aw = p1.y;   // self term h'[n]
    }

    int beg = g_rowptr[n];
    int cnt = g_cnt[n];
    int end = beg + cnt;

    int idx = beg;
    for (; idx + 3 < end; idx += 4) {                 // 4-way MLP
        int s0 = g_col[idx];
        int s1 = g_col[idx + 1];
        int s2 = g_col[idx + 2];
        int s3 = g_col[idx + 3];
        uint2 v0 = ((const uint2*)(h + (size_t)s0 * HID))[lane];
        uint2 v1 = ((const uint2*)(h + (size_t)s1 * HID))[lane];
        uint2 v2 = ((const uint2*)(h + (size_t)s2 * HID))[lane];
        uint2 v3 = ((const uint2*)(h + (size_t)s3 * HID))[lane];
        float2 a0 = __half22float2(*(const __half2*)&v0.x);
        float2 b0 = __half22float2(*(const __half2*)&v0.y);
        float2 a1 = __half22float2(*(const __half2*)&v1.x);
        float2 b1 = __half22float2(*(const __half2*)&v1.y);
        float2 a2 = __half22float2(*(const __half2*)&v2.x);
        float2 b2 = __half22float2(*(const __half2*)&v2.y);
        float2 a3 = __half22float2(*(const __half2*)&v3.x);
        float2 b3 = __half22float2(*(const __half2*)&v3.y);
        ax += (a0.x + a1.x) + (a2.x + a3.x);
        ay += (a0.y + a1.y) + (a2.y + a3.y);
        az += (b0.x + b1.x) + (b2.x + b3.x);
        aw += (b0.y + b1.y) + (b2.y + b3.y);
    }
    for (; idx < end; idx++) {
        int s0 = g_col[idx];
        uint2 v0 = ((const uint2*)(h + (size_t)s0 * HID))[lane];
        float2 a0 = __half22float2(*(const __half2*)&v0.x);
        float2 b0 = __half22float2(*(const __half2*)&v0.y);
        ax += a0.x; ay += a0.y; az += b0.x; aw += b0.y;
    }

    float wn = rsqrtf((float)(cnt + 1));
    float4 bv = ((const float4*)bias)[lane];
    float4 r;
    r.x = fmaxf(wn * ax + bv.x, 0.f);
    r.y = fmaxf(wn * ay + bv.y, 0.f);
    r.z = fmaxf(wn * az + bv.z, 0.f);
    r.w = fmaxf(wn * aw + bv.w, 0.f);

    if (!Wout) {
        uint2 o;
        *(__half2*)&o.x = __floats2half2_rn(r.x, r.y);
        *(__half2*)&o.y = __floats2half2_rn(r.z, r.w);
        ((uint2*)(g_bufX + (size_t)n * HID))[lane] = o;
    } else {
        int kb = lane * 4;
        #pragma unroll
        for (int c = 0; c < NC; c++) {
            float s = r.x * Ws[(kb + 0) * NC + c]
                    + r.y * Ws[(kb + 1) * NC + c]
                    + r.z * Ws[(kb + 2) * NC + c]
                    + r.w * Ws[(kb + 3) * NC + c];
            #pragma unroll
            for (int off = 16; off; off >>= 1)
                s += __shfl_down_sync(0xffffffffu, s, off);
            if (lane == 0) out[(size_t)n * NC + c] = s + bs[c];
        }
    }
}

// ---------------- launch ----------------
extern "C" void kernel_launch(void* const* d_in, const int* in_sizes, int n_in,
                              void* d_out, int out_size) {
    const int*   src  = (const int*)d_in[0];          // edge_index[0]
    const int*   dst  = src + NE;                     // edge_index[1]
    const float* emb  = (const float*)d_in[1];
    const float* W1   = (const float*)d_in[2];
    const float* b1   = (const float*)d_in[3];
    const float* W2   = (const float*)d_in[4];
    const float* b2   = (const float*)d_in[5];
    const float* Wout = (const float*)d_in[6];
    const float* bout = (const float*)d_in[7];
    float* out = (float*)d_out;

    const int SCAN_BLKS  = (NN + 511) / 512;          // 196
    const int EDGE4_BLKS = (NE / 4 + 255) / 256;      // 1563
    const int GEMM_BLKS  = (NN + 127) / 128;          // 782
    const int G2H0_BLKS  = HALF0 / 128;               // 391
    const int G2H1_BLKS  = (HALF1 + 127) / 128;       // 391
    const int AGG_BLKS   = (NN * 32) / 256;           // 12500
    const int A1H0_BLKS  = (HALF0 * 32) / 256;        // 6256
    const int A1H1_BLKS  = (HALF1 * 32) / 256;        // 6244

    static cudaStream_t s2 = nullptr;
    static cudaEvent_t evF = nullptr, evI = nullptr, evJ = nullptr;
    static cudaEvent_t evA0 = nullptr, evA1 = nullptr, evG1 = nullptr;
    static void* cntAddr = nullptr;
    if (!s2) {
        cudaFuncSetAttribute(k_gemm_mma, cudaFuncAttributeMaxDynamicSharedMemorySize, DSMEM_SZ);
        cudaStreamCreateWithFlags(&s2, cudaStreamNonBlocking);
        cudaEventCreateWithFlags(&evF, cudaEventDisableTiming);
        cudaEventCreateWithFlags(&evI, cudaEventDisableTiming);
        cudaEventCreateWithFlags(&evJ, cudaEventDisableTiming);
        cudaEventCreateWithFlags(&evA0, cudaEventDisableTiming);
        cudaEventCreateWithFlags(&evA1, cudaEventDisableTiming);
        cudaEventCreateWithFlags(&evG1, cudaEventDisableTiming);
        cudaGetSymbolAddress(&cntAddr, g_cnt);
    }

    // Fork: side stream starts weight images immediately (input-only deps)
    cudaEventRecord(evF, 0);
    cudaStreamWaitEvent(s2, evF, 0);
    k_wimg<<<32, 256, 0, s2>>>(W1, 0);
    k_wimg<<<32, 256, 0, s2>>>(W2, 1);

    // Main stream: counts (GEMM1's only prep dependency — epilogue rsqrt inline)
    cudaMemsetAsync(cntAddr, 0, NN * sizeof(int), 0);
    k_count<<<EDGE4_BLKS, 256>>>(dst);
    cudaEventRecord(evI, 0);

    // Side stream: GEMM1 overlaps remaining CSR build
    cudaStreamWaitEvent(s2, evI, 0);
    k_gemm_mma<<<GEMM_BLKS, 256, DSMEM_SZ, s2>>>(emb, 0, 0);
    cudaEventRecord(evJ, s2);

    // Main stream: rest of CSR build
    k_scanA<<<SCAN_BLKS, 512>>>();
    k_scanB<<<1, 256>>>(SCAN_BLKS);
    k_scanC<<<SCAN_BLKS, 512>>>();
    k_place<<<EDGE4_BLKS, 256>>>(src, dst);

    // Join; then software-pipeline agg1 halves with GEMM2 halves
    cudaStreamWaitEvent(0, evJ, 0);
    k_agg<<<A1H0_BLKS, 256>>>(0, 0, b1, nullptr, nullptr, nullptr);
    cudaEventRecord(evA0, 0);

    cudaStreamWaitEvent(s2, evA0, 0);
    k_gemm_mma<<<G2H0_BLKS, 256, DSMEM_SZ, s2>>>(nullptr, 1, 0);       // overlaps agg1(half1)

    k_agg<<<A1H1_BLKS, 256>>>(0, HALF0, b1, nullptr, nullptr, nullptr);
    cudaEventRecord(evA1, 0);

    cudaStreamWaitEvent(s2, evA1, 0);
    k_gemm_mma<<<G2H1_BLKS, 256, DSMEM_SZ, s2>>>(nullptr, 1, HALF0);
    cudaEventRecord(evG1, s2);

    // Final: layer-2 agg + fused output projection
    cudaStreamWaitEvent(0, evG1, 0);
    k_agg<<<AGG_BLKS, 256>>>(1, 0, b2, Wout, bout, out);
}

// round 9
// speedup vs baseline: 1.0081x; 1.0081x over previous
#include <cuda_runtime.h>
#include <cuda_bf16.h>
#include <cuda_fp16.h>
#include <math.h>
#include <cstdint>

#define NN 100000
#define HID 128
#define NE 1600000
#define NC 10

// ---------------- scratch (device globals; no allocation allowed) -------------
__device__ int    g_cnt[NN];
__device__ int    g_rowptr[NN];
__device__ int    g_col[NE];
__device__ int    g_pos[NE];                   // intra-segment position per edge
__device__ int    g_blockSums[256];
__device__ __half g_bufH1[(size_t)NN * HID];   // layer-1 h' = invs*h (fp16)
__device__ __half g_bufH2[(size_t)NN * HID];   // layer-2 h' (fp16)
__device__ __half g_bufX[(size_t)NN * HID];    // layer-1 activation x (fp16)
// bf16 hi/lo weight images, layout [n][k/2] u32 pairs
__device__ uint32_t g_W1hi[128 * 64];
__device__ uint32_t g_W1lo[128 * 64];
__device__ uint32_t g_W2hi[128 * 64];
__device__ uint32_t g_W2lo[128 * 64];

__device__ __forceinline__ uint32_t smem_u32(const void* p) {
    uint32_t a;
    asm("{ .reg .u64 t; cvta.to.shared.u64 t, %1; cvt.u32.u64 %0, t; }" : "=r"(a) : "l"(p));
    return a;
}

// ---------------- degree histogram + position record (single atomic pass) ----
__global__ void k_count(const int* __restrict__ dst) {
    int e4 = blockIdx.x * blockDim.x + threadIdx.x;
    if (e4 < NE / 4) {
        int4 d = ((const int4*)dst)[e4];
        int4 p;
        p.x = atomicAdd(&g_cnt[d.x], 1);
        p.y = atomicAdd(&g_cnt[d.y], 1);
        p.z = atomicAdd(&g_cnt[d.z], 1);
        p.w = atomicAdd(&g_cnt[d.w], 1);
        ((int4*)g_pos)[e4] = p;
    }
}

// ---------------- exclusive scan (3-phase) ----------------
__global__ void k_scanA() {
    __shared__ int s[512];
    int i = blockIdx.x * 512 + threadIdx.x;
    int v = (i < NN) ? g_cnt[i] : 0;
    s[threadIdx.x] = v;
    __syncthreads();
    #pragma unroll
    for (int off = 1; off < 512; off <<= 1) {
        int t = (threadIdx.x >= off) ? s[threadIdx.x - off] : 0;
        __syncthreads();
        s[threadIdx.x] += t;
        __syncthreads();
    }
    if (i < NN) g_rowptr[i] = s[threadIdx.x] - v;        // exclusive
    if (threadIdx.x == 511) g_blockSums[blockIdx.x] = s[511];
}

__global__ void k_scanB(int nblocks) {
    __shared__ int s[256];
    int t = threadIdx.x;
    int v = (t < nblocks) ? g_blockSums[t] : 0;
    s[t] = v;
    __syncthreads();
    #pragma unroll
    for (int off = 1; off < 256; off <<= 1) {
        int u = (t >= off) ? s[t - off] : 0;
        __syncthreads();
        s[t] += u;
        __syncthreads();
    }
    if (t < nblocks) g_blockSums[t] = s[t] - v;           // exclusive
}

__global__ void k_scanC() {
    int i = blockIdx.x * 512 + threadIdx.x;
    if (i < NN) g_rowptr[i] += g_blockSums[blockIdx.x];
}

// ---------------- CSR place (no atomics) ----------------
__global__ void k_place(const int* __restrict__ src, const int* __restrict__ dst) {
    int e4 = blockIdx.x * blockDim.x + threadIdx.x;
    if (e4 < NE / 4) {
        int4 s = ((const int4*)src)[e4];
        int4 d = ((const int4*)dst)[e4];
        int4 p = ((const int4*)g_pos)[e4];
        g_col[g_rowptr[d.x] + p.x] = s.x;
        g_col[g_rowptr[d.y] + p.y] = s.y;
        g_col[g_rowptr[d.z] + p.z] = s.z;
        g_col[g_rowptr[d.w] + p.w] = s.w;
    }
}

// ---------------- weight image precompute ----------------
__global__ void k_wimg(const float* __restrict__ W, int layer) {
    uint32_t* hiImg = (layer == 0 ? g_W1hi : g_W2hi);
    uint32_t* loImg = (layer == 0 ? g_W1lo : g_W2lo);
    int idx = blockIdx.x * blockDim.x + threadIdx.x;      // 0..8191 (pairs)
    if (idx >= 128 * 64) return;
    int n = idx >> 6, cp = idx & 63;
    int k0 = 2 * cp;
    float w0 = W[(size_t)k0 * HID + n];
    float w1 = W[(size_t)(k0 + 1) * HID + n];
    __nv_bfloat16 h0 = __float2bfloat16(w0), h1 = __float2bfloat16(w1);
    __nv_bfloat16 l0 = __float2bfloat16(w0 - __bfloat162float(h0));
    __nv_bfloat16 l1 = __float2bfloat16(w1 - __bfloat162float(h1));
    hiImg[idx] = (uint32_t)__bfloat16_as_ushort(h0) | ((uint32_t)__bfloat16_as_ushort(h1) << 16);
    loImg[idx] = (uint32_t)__bfloat16_as_ushort(l0) | ((uint32_t)__bfloat16_as_ushort(l1) << 16);
}

// ---------------- mma.sync bf16x3 GEMM with ldmatrix fragment loads ----------
// h'[r][:] = rsqrt(cnt[r]+1) * (A[r][:] @ W), stored fp16.
#define ROWW 68
#define MAT_W (128 * ROWW)
#define DSMEM_SZ (4 * MAT_W * 4)

__device__ __forceinline__ void mma_bf16(float* d, uint32_t a0, uint32_t a1,
                                         uint32_t a2, uint32_t a3,
                                         uint32_t b0, uint32_t b1) {
    asm volatile(
        "mma.sync.aligned.m16n8k16.row.col.f32.bf16.bf16.f32 "
        "{%0,%1,%2,%3}, {%4,%5,%6,%7}, {%8,%9}, {%0,%1,%2,%3};\n"
        : "+f"(d[0]), "+f"(d[1]), "+f"(d[2]), "+f"(d[3])
        : "r"(a0), "r"(a1), "r"(a2), "r"(a3), "r"(b0), "r"(b1));
}

__device__ __forceinline__ void ldsm_x4(uint32_t& r0, uint32_t& r1, uint32_t& r2,
                                        uint32_t& r3, uint32_t addr) {
    asm volatile("ldmatrix.sync.aligned.m8n8.x4.shared.b16 {%0,%1,%2,%3}, [%4];"
                 : "=r"(r0), "=r"(r1), "=r"(r2), "=r"(r3) : "r"(addr));
}

__global__ void __launch_bounds__(256, 1) k_gemm_mma(const float* Af32, int layer, int rowBase) {
    extern __shared__ uint32_t sm[];
    uint32_t* sAhi = sm;
    uint32_t* sAlo = sm + MAT_W;
    uint32_t* sWhi = sm + 2 * MAT_W;
    uint32_t* sWlo = sm + 3 * MAT_W;

    const uint32_t* whi = (layer == 0 ? g_W1hi : g_W2hi);
    const uint32_t* wlo = (layer == 0 ? g_W1lo : g_W2lo);
    __half* outH = (layer == 0 ? g_bufH1 : g_bufH2);

    int tid = threadIdx.x;
    int wid = tid >> 5, lane = tid & 31;
    int g = lane >> 2, t = lane & 3;
    int blockRow = rowBase + blockIdx.x * 128;

    // Stage W images
    #pragma unroll
    for (int i = 0; i < 32; i++) {
        int idx = tid + i * 256;
        int row = idx >> 6, c = idx & 63;
        sWhi[row * ROWW + c] = whi[idx];
        sWlo[row * ROWW + c] = wlo[idx];
    }

    // Convert A tile (fp32 input or fp16 g_bufX) -> bf16 hi/lo
    #pragma unroll
    for (int i = 0; i < 32; i++) {
        int idx = tid + i * 256;
        int row = idx >> 6, c = idx & 63;
        int gr = blockRow + row;
        float2 v = make_float2(0.f, 0.f);
        if (gr < NN) {
            if (Af32) {
                v = *(const float2*)&Af32[(size_t)gr * HID + 2 * c];
            } else {
                uint32_t u = ((const uint32_t*)(g_bufX + (size_t)gr * HID))[c];
                v = __half22float2(*(const __half2*)&u);
            }
        }
        __nv_bfloat16 h0 = __float2bfloat16(v.x), h1 = __float2bfloat16(v.y);
        __nv_bfloat16 l0 = __float2bfloat16(v.x - __bfloat162float(h0));
        __nv_bfloat16 l1 = __float2bfloat16(v.y - __bfloat162float(h1));
        sAhi[row * ROWW + c] = (uint32_t)__bfloat16_as_ushort(h0) | ((uint32_t)__bfloat16_as_ushort(h1) << 16);
        sAlo[row * ROWW + c] = (uint32_t)__bfloat16_as_ushort(l0) | ((uint32_t)__bfloat16_as_ushort(l1) << 16);
    }
    __syncthreads();

    float acc[16][4];
    #pragma unroll
    for (int j = 0; j < 16; j++)
        #pragma unroll
        for (int q = 0; q < 4; q++) acc[j][q] = 0.f;

    // ldmatrix per-lane base addresses
    int grp = lane >> 3, l8 = lane & 7;
    uint32_t base = smem_u32(sm);
    // A x4: grp0 -> rows m0-7/k0, grp1 -> m8-15/k0, grp2 -> m0-7/k+8, grp3 -> m8-15/k+8
    uint32_t aOff = (uint32_t)((wid * 16 + (grp & 1) * 8 + l8) * ROWW + (grp >> 1) * 4) * 4;
    uint32_t aHiAddr = base + aOff;                       // sAhi at word offset 0
    uint32_t aLoAddr = base + MAT_W * 4 + aOff;
    // W x4 (j-pair): grp0 -> n rows 8j/k0, grp1 -> 8j/k+8, grp2 -> 8(j+1)/k0, grp3 -> 8(j+1)/k+8
    uint32_t wOff = (uint32_t)(((grp >> 1) * 8 + l8) * ROWW + (grp & 1) * 4) * 4;
    uint32_t wHiAddr = base + 2 * MAT_W * 4 + wOff;
    uint32_t wLoAddr = base + 3 * MAT_W * 4 + wOff;

    #pragma unroll
    for (int kc = 0; kc < 8; kc++) {
        uint32_t kB = kc * 32;                            // 8 words per k-chunk
        uint32_t ah0, ah1, ah2, ah3, al0, al1, al2, al3;
        ldsm_x4(ah0, ah1, ah2, ah3, aHiAddr + kB);
        ldsm_x4(al0, al1, al2, al3, aLoAddr + kB);
        #pragma unroll
        for (int jp = 0; jp < 8; jp++) {
            uint32_t jB = (uint32_t)(jp * 16 * ROWW) * 4 + kB;
            uint32_t bh0, bh1, bh2, bh3, bl0, bl1, bl2, bl3;
            ldsm_x4(bh0, bh1, bh2, bh3, wHiAddr + jB);
            ldsm_x4(bl0, bl1, bl2, bl3, wLoAddr + jB);
            mma_bf16(acc[2 * jp],     ah0, ah1, ah2, ah3, bh0, bh1);
            mma_bf16(acc[2 * jp + 1], ah0, ah1, ah2, ah3, bh2, bh3);
            mma_bf16(acc[2 * jp],     al0, al1, al2, al3, bh0, bh1);
            mma_bf16(acc[2 * jp + 1], al0, al1, al2, al3, bh2, bh3);
            mma_bf16(acc[2 * jp],     ah0, ah1, ah2, ah3, bl0, bl1);
            mma_bf16(acc[2 * jp + 1], ah0, ah1, ah2, ah3, bl2, bl3);
        }
    }

    // Epilogue: scale by rsqrt(cnt+1) computed inline, store fp16 h'
    int gr0 = blockRow + wid * 16 + g;
    int gr1 = gr0 + 8;
    float wn0 = (gr0 < NN) ? rsqrtf((float)(g_cnt[gr0] + 1)) : 0.f;
    float wn1 = (gr1 < NN) ? rsqrtf((float)(g_cnt[gr1] + 1)) : 0.f;
    #pragma unroll
    for (int j = 0; j < 16; j++) {
        int col = j * 8 + 2 * t;
        if (gr0 < NN)
            *(__half2*)&outH[(size_t)gr0 * HID + col] =
                __floats2half2_rn(wn0 * acc[j][0], wn0 * acc[j][1]);
        if (gr1 < NN)
            *(__half2*)&outH[(size_t)gr1 * HID + col] =
                __floats2half2_rn(wn1 * acc[j][2], wn1 * acc[j][3]);
    }
}

// ---------------- gather-aggregate + bias + relu (+ fused output proj) -------
// agg[n] = rsqrt(cnt[n]+1) * sum_{s in N(n) U {n}} h'[s];  x = relu(agg + b)
__global__ void k_agg(int layer, const float* __restrict__ bias,
                      const float* __restrict__ Wout, const float* __restrict__ bout,
                      float* __restrict__ out) {
    const __half* h = (layer == 0 ? g_bufH1 : g_bufH2);
    __shared__ float Ws[HID * NC];
    __shared__ float bs[NC];

    int tid = threadIdx.x;
    if (Wout) {
        for (int i = tid; i < HID * NC; i += blockDim.x) Ws[i] = Wout[i];
        if (tid < NC) bs[tid] = bout[tid];
        __syncthreads();
    }

    int n = (blockIdx.x * blockDim.x + tid) >> 5;     // grid exact: 100000 warps
    int lane = tid & 31;

    float ax, ay, az, aw;
    {
        uint2 v = ((const uint2*)(h + (size_t)n * HID))[lane];
        float2 p0 = __half22float2(*(const __half2*)&v.x);
        float2 p1 = __half22float2(*(const __half2*)&v.y);
        ax = p0.x; ay = p0.y; az = p1.x; aw = p1.y;   // self term h'[n]
    }

    int beg = g_rowptr[n];
    int cnt = g_cnt[n];
    int end = beg + cnt;

    int idx = beg;
    for (; idx + 3 < end; idx += 4) {                 // 4-way MLP
        int s0 = g_col[idx];
        int s1 = g_col[idx + 1];
        int s2 = g_col[idx + 2];
        int s3 = g_col[idx + 3];
        uint2 v0 = ((const uint2*)(h + (size_t)s0 * HID))[lane];
        uint2 v1 = ((const uint2*)(h + (size_t)s1 * HID))[lane];
        uint2 v2 = ((const uint2*)(h + (size_t)s2 * HID))[lane];
        uint2 v3 = ((const uint2*)(h + (size_t)s3 * HID))[lane];
        float2 a0 = __half22float2(*(const __half2*)&v0.x);
        float2 b0 = __half22float2(*(const __half2*)&v0.y);
        float2 a1 = __half22float2(*(const __half2*)&v1.x);
        float2 b1 = __half22float2(*(const __half2*)&v1.y);
        float2 a2 = __half22float2(*(const __half2*)&v2.x);
        float2 b2 = __half22float2(*(const __half2*)&v2.y);
        float2 a3 = __half22float2(*(const __half2*)&v3.x);
        float2 b3 = __half22float2(*(const __half2*)&v3.y);
        ax += (a0.x + a1.x) + (a2.x + a3.x);
        ay += (a0.y + a1.y) + (a2.y + a3.y);
        az += (b0.x + b1.x) + (b2.x + b3.x);
        aw += (b0.y + b1.y) + (b2.y + b3.y);
    }
    for (; idx < end; idx++) {
        int s0 = g_col[idx];
        uint2 v0 = ((const uint2*)(h + (size_t)s0 * HID))[lane];
        float2 a0 = __half22float2(*(const __half2*)&v0.x);
        float2 b0 = __half22float2(*(const __half2*)&v0.y);
        ax += a0.x; ay += a0.y; az += b0.x; aw += b0.y;
    }

    float wn = rsqrtf((float)(cnt + 1));
    float4 bv = ((const float4*)bias)[lane];
    float4 r;
    r.x = fmaxf(wn * ax + bv.x, 0.f);
    r.y = fmaxf(wn * ay + bv.y, 0.f);
    r.z = fmaxf(wn * az + bv.z, 0.f);
    r.w = fmaxf(wn * aw + bv.w, 0.f);

    if (!Wout) {
        uint2 o;
        *(__half2*)&o.x = __floats2half2_rn(r.x, r.y);
        *(__half2*)&o.y = __floats2half2_rn(r.z, r.w);
        ((uint2*)(g_bufX + (size_t)n * HID))[lane] = o;
    } else {
        int kb = lane * 4;
        #pragma unroll
        for (int c = 0; c < NC; c++) {
            float s = r.x * Ws[(kb + 0) * NC + c]
                    + r.y * Ws[(kb + 1) * NC + c]
                    + r.z * Ws[(kb + 2) * NC + c]
                    + r.w * Ws[(kb + 3) * NC + c];
            #pragma unroll
            for (int off = 16; off; off >>= 1)
                s += __shfl_down_sync(0xffffffffu, s, off);
            if (lane == 0) out[(size_t)n * NC + c] = s + bs[c];
        }
    }
}

// ---------------- launch ----------------
extern "C" void kernel_launch(void* const* d_in, const int* in_sizes, int n_in,
                              void* d_out, int out_size) {
    const int*   src  = (const int*)d_in[0];          // edge_index[0]
    const int*   dst  = src + NE;                     // edge_index[1]
    const float* emb  = (const float*)d_in[1];
    const float* W1   = (const float*)d_in[2];
    const float* b1   = (const float*)d_in[3];
    const float* W2   = (const float*)d_in[4];
    const float* b2   = (const float*)d_in[5];
    const float* Wout = (const float*)d_in[6];
    const float* bout = (const float*)d_in[7];
    float* out = (float*)d_out;

    const int SCAN_BLKS  = (NN + 511) / 512;          // 196
    const int EDGE4_BLKS = (NE / 4 + 255) / 256;      // 1563
    const int GEMM_BLKS  = (NN + 127) / 128;          // 782
    const int AGG_BLKS   = (NN * 32) / 256;           // 12500

    static cudaStream_t s2 = nullptr;
    static cudaEvent_t evF = nullptr, evI = nullptr, evJ = nullptr;
    static void* cntAddr = nullptr;
    if (!s2) {
        cudaFuncSetAttribute(k_gemm_mma, cudaFuncAttributeMaxDynamicSharedMemorySize, DSMEM_SZ);
        cudaStreamCreateWithFlags(&s2, cudaStreamNonBlocking);
        cudaEventCreateWithFlags(&evF, cudaEventDisableTiming);
        cudaEventCreateWithFlags(&evI, cudaEventDisableTiming);
        cudaEventCreateWithFlags(&evJ, cudaEventDisableTiming);
        cudaGetSymbolAddress(&cntAddr, g_cnt);
    }

    // Fork: side stream starts weight images immediately (input-only deps)
    cudaEventRecord(evF, 0);
    cudaStreamWaitEvent(s2, evF, 0);
    k_wimg<<<32, 256, 0, s2>>>(W1, 0);
    k_wimg<<<32, 256, 0, s2>>>(W2, 1);

    // Main stream: counts (GEMM1's only prep dependency — epilogue rsqrt inline)
    cudaMemsetAsync(cntAddr, 0, NN * sizeof(int), 0);
    k_count<<<EDGE4_BLKS, 256>>>(dst);
    cudaEventRecord(evI, 0);

    // Side stream: GEMM1 overlaps remaining CSR build
    cudaStreamWaitEvent(s2, evI, 0);
    k_gemm_mma<<<GEMM_BLKS, 256, DSMEM_SZ, s2>>>(emb, 0, 0);
    cudaEventRecord(evJ, s2);

    // Main stream: rest of CSR build
    k_scanA<<<SCAN_BLKS, 512>>>();
    k_scanB<<<1, 256>>>(SCAN_BLKS);
    k_scanC<<<SCAN_BLKS, 512>>>();
    k_place<<<EDGE4_BLKS, 256>>>(src, dst);

    // Join, then layer-1 agg -> layer-2 GEMM -> layer-2 agg + output proj
    cudaStreamWaitEvent(0, evJ, 0);
    k_agg<<<AGG_BLKS, 256>>>(0, b1, nullptr, nullptr, nullptr);
    k_gemm_mma<<<GEMM_BLKS, 256, DSMEM_SZ>>>(nullptr, 1, 0);
    k_agg<<<AGG_BLKS, 256>>>(1, b2, Wout, bout, out);
}

// round 10
// speedup vs baseline: 1.0245x; 1.0163x over previous
#include <cuda_runtime.h>
#include <cuda_bf16.h>
#include <cuda_fp16.h>
#include <math.h>
#include <cstdint>

#define NN 100000
#define HID 128
#define NE 1600000
#define NC 10

// ---------------- scratch (device globals; no allocation allowed) -------------
__device__ int    g_cnt[NN];
__device__ int    g_rowptr[NN];
__device__ int    g_col[NE];
__device__ int    g_pos[NE];                   // intra-segment position per edge
__device__ int    g_blockSums[256];
__device__ __half g_bufH1[(size_t)NN * HID];   // layer-1 h' = invs*h (fp16)
__device__ __half g_bufH2[(size_t)NN * HID];   // layer-2 h' (fp16)
__device__ __half g_bufX[(size_t)NN * HID];    // layer-1 activation x (fp16)
// bf16 hi/lo weight images, layout [n][k/2] u32 pairs
__device__ uint32_t g_W1hi[128 * 64];
__device__ uint32_t g_W1lo[128 * 64];
__device__ uint32_t g_W2hi[128 * 64];
__device__ uint32_t g_W2lo[128 * 64];

__device__ __forceinline__ uint32_t smem_u32(const void* p) {
    uint32_t a;
    asm("{ .reg .u64 t; cvta.to.shared.u64 t, %1; cvt.u32.u64 %0, t; }" : "=r"(a) : "l"(p));
    return a;
}

// ---------------- degree histogram + position record (single atomic pass) ----
__global__ void k_count(const int* __restrict__ dst) {
    int e4 = blockIdx.x * blockDim.x + threadIdx.x;
    if (e4 < NE / 4) {
        int4 d = ((const int4*)dst)[e4];
        int4 p;
        p.x = atomicAdd(&g_cnt[d.x], 1);
        p.y = atomicAdd(&g_cnt[d.y], 1);
        p.z = atomicAdd(&g_cnt[d.z], 1);
        p.w = atomicAdd(&g_cnt[d.w], 1);
        ((int4*)g_pos)[e4] = p;
    }
}

// ---------------- exclusive scan (3-phase) ----------------
__global__ void k_scanA() {
    __shared__ int s[512];
    int i = blockIdx.x * 512 + threadIdx.x;
    int v = (i < NN) ? g_cnt[i] : 0;
    s[threadIdx.x] = v;
    __syncthreads();
    #pragma unroll
    for (int off = 1; off < 512; off <<= 1) {
        int t = (threadIdx.x >= off) ? s[threadIdx.x - off] : 0;
        __syncthreads();
        s[threadIdx.x] += t;
        __syncthreads();
    }
    if (i < NN) g_rowptr[i] = s[threadIdx.x] - v;        // exclusive
    if (threadIdx.x == 511) g_blockSums[blockIdx.x] = s[511];
}

__global__ void k_scanB(int nblocks) {
    __shared__ int s[256];
    int t = threadIdx.x;
    int v = (t < nblocks) ? g_blockSums[t] : 0;
    s[t] = v;
    __syncthreads();
    #pragma unroll
    for (int off = 1; off < 256; off <<= 1) {
        int u = (t >= off) ? s[t - off] : 0;
        __syncthreads();
        s[t] += u;
        __syncthreads();
    }
    if (t < nblocks) g_blockSums[t] = s[t] - v;           // exclusive
}

__global__ void k_scanC() {
    int i = blockIdx.x * 512 + threadIdx.x;
    if (i < NN) g_rowptr[i] += g_blockSums[blockIdx.x];
}

// ---------------- CSR place (no atomics) ----------------
__global__ void k_place(const int* __restrict__ src, const int* __restrict__ dst) {
    int e4 = blockIdx.x * blockDim.x + threadIdx.x;
    if (e4 < NE / 4) {
        int4 s = ((const int4*)src)[e4];
        int4 d = ((const int4*)dst)[e4];
        int4 p = ((const int4*)g_pos)[e4];
        g_col[g_rowptr[d.x] + p.x] = s.x;
        g_col[g_rowptr[d.y] + p.y] = s.y;
        g_col[g_rowptr[d.z] + p.z] = s.z;
        g_col[g_rowptr[d.w] + p.w] = s.w;
    }
}

// ---------------- weight image precompute ----------------
__global__ void k_wimg(const float* __restrict__ W, int layer) {
    uint32_t* hiImg = (layer == 0 ? g_W1hi : g_W2hi);
    uint32_t* loImg = (layer == 0 ? g_W1lo : g_W2lo);
    int idx = blockIdx.x * blockDim.x + threadIdx.x;      // 0..8191 (pairs)
    if (idx >= 128 * 64) return;
    int n = idx >> 6, cp = idx & 63;
    int k0 = 2 * cp;
    float w0 = W[(size_t)k0 * HID + n];
    float w1 = W[(size_t)(k0 + 1) * HID + n];
    __nv_bfloat16 h0 = __float2bfloat16(w0), h1 = __float2bfloat16(w1);
    __nv_bfloat16 l0 = __float2bfloat16(w0 - __bfloat162float(h0));
    __nv_bfloat16 l1 = __float2bfloat16(w1 - __bfloat162float(h1));
    hiImg[idx] = (uint32_t)__bfloat16_as_ushort(h0) | ((uint32_t)__bfloat16_as_ushort(h1) << 16);
    loImg[idx] = (uint32_t)__bfloat16_as_ushort(l0) | ((uint32_t)__bfloat16_as_ushort(l1) << 16);
}

// ---------------- mma.sync bf16x3 GEMM, 512 threads (16 warps) ---------------
// Warp layout: rowGrp = wid&7 (16 rows), nHalf = wid>>3 (64-col half).
// h'[r][:] = rsqrt(cnt[r]+1) * (A[r][:] @ W), stored fp16.
#define ROWW 68
#define MAT_W (128 * ROWW)
#define DSMEM_SZ (4 * MAT_W * 4)

__device__ __forceinline__ void mma_bf16(float* d, uint32_t a0, uint32_t a1,
                                         uint32_t a2, uint32_t a3,
                                         uint32_t b0, uint32_t b1) {
    asm volatile(
        "mma.sync.aligned.m16n8k16.row.col.f32.bf16.bf16.f32 "
        "{%0,%1,%2,%3}, {%4,%5,%6,%7}, {%8,%9}, {%0,%1,%2,%3};\n"
        : "+f"(d[0]), "+f"(d[1]), "+f"(d[2]), "+f"(d[3])
        : "r"(a0), "r"(a1), "r"(a2), "r"(a3), "r"(b0), "r"(b1));
}

__device__ __forceinline__ void ldsm_x4(uint32_t& r0, uint32_t& r1, uint32_t& r2,
                                        uint32_t& r3, uint32_t addr) {
    asm volatile("ldmatrix.sync.aligned.m8n8.x4.shared.b16 {%0,%1,%2,%3}, [%4];"
                 : "=r"(r0), "=r"(r1), "=r"(r2), "=r"(r3) : "r"(addr));
}

__global__ void __launch_bounds__(512, 1) k_gemm_mma(const float* Af32, int layer, int rowBase) {
    extern __shared__ uint32_t sm[];
    uint32_t* sAhi = sm;
    uint32_t* sAlo = sm + MAT_W;
    uint32_t* sWhi = sm + 2 * MAT_W;
    uint32_t* sWlo = sm + 3 * MAT_W;

    const uint32_t* whi = (layer == 0 ? g_W1hi : g_W2hi);
    const uint32_t* wlo = (layer == 0 ? g_W1lo : g_W2lo);
    __half* outH = (layer == 0 ? g_bufH1 : g_bufH2);

    int tid = threadIdx.x;
    int wid = tid >> 5, lane = tid & 31;
    int g = lane >> 2, t = lane & 3;
    int rowGrp = wid & 7;                     // which 16-row stripe
    int nHalf = wid >> 3;                     // which 64-col half
    int blockRow = rowBase + blockIdx.x * 128;

    // Stage W images
    #pragma unroll
    for (int i = 0; i < 16; i++) {
        int idx = tid + i * 512;
        int row = idx >> 6, c = idx & 63;
        sWhi[row * ROWW + c] = whi[idx];
        sWlo[row * ROWW + c] = wlo[idx];
    }

    // Convert A tile (fp32 input or fp16 g_bufX) -> bf16 hi/lo
    #pragma unroll
    for (int i = 0; i < 16; i++) {
        int idx = tid + i * 512;
        int row = idx >> 6, c = idx & 63;
        int gr = blockRow + row;
        float2 v = make_float2(0.f, 0.f);
        if (gr < NN) {
            if (Af32) {
                v = *(const float2*)&Af32[(size_t)gr * HID + 2 * c];
            } else {
                uint32_t u = ((const uint32_t*)(g_bufX + (size_t)gr * HID))[c];
                v = __half22float2(*(const __half2*)&u);
            }
        }
        __nv_bfloat16 h0 = __float2bfloat16(v.x), h1 = __float2bfloat16(v.y);
        __nv_bfloat16 l0 = __float2bfloat16(v.x - __bfloat162float(h0));
        __nv_bfloat16 l1 = __float2bfloat16(v.y - __bfloat162float(h1));
        sAhi[row * ROWW + c] = (uint32_t)__bfloat16_as_ushort(h0) | ((uint32_t)__bfloat16_as_ushort(h1) << 16);
        sAlo[row * ROWW + c] = (uint32_t)__bfloat16_as_ushort(l0) | ((uint32_t)__bfloat16_as_ushort(l1) << 16);
    }
    __syncthreads();

    float acc[8][4];
    #pragma unroll
    for (int j = 0; j < 8; j++)
        #pragma unroll
        for (int q = 0; q < 4; q++) acc[j][q] = 0.f;

    // ldmatrix per-lane base addresses
    int grp = lane >> 3, l8 = lane & 7;
    uint32_t base = smem_u32(sm);
    // A x4: grp0 -> m0-7/k0, grp1 -> m8-15/k0, grp2 -> m0-7/k+8, grp3 -> m8-15/k+8
    uint32_t aOff = (uint32_t)((rowGrp * 16 + (grp & 1) * 8 + l8) * ROWW + (grp >> 1) * 4) * 4;
    uint32_t aHiAddr = base + aOff;
    uint32_t aLoAddr = base + MAT_W * 4 + aOff;
    // W x4 (j-pair): grp0 -> n rows +0/k0, grp1 -> +0/k+8, grp2 -> +8/k0, grp3 -> +8/k+8
    uint32_t wOff = (uint32_t)((nHalf * 64 + (grp >> 1) * 8 + l8) * ROWW + (grp & 1) * 4) * 4;
    uint32_t wHiAddr = base + 2 * MAT_W * 4 + wOff;
    uint32_t wLoAddr = base + 3 * MAT_W * 4 + wOff;

    #pragma unroll
    for (int kc = 0; kc < 8; kc++) {
        uint32_t kB = kc * 32;                // 8 words per k-chunk
        uint32_t ah0, ah1, ah2, ah3, al0, al1, al2, al3;
        ldsm_x4(ah0, ah1, ah2, ah3, aHiAddr + kB);
        ldsm_x4(al0, al1, al2, al3, aLoAddr + kB);
        #pragma unroll
        for (int jp = 0; jp < 4; jp++) {
            uint32_t jB = (uint32_t)(jp * 16 * ROWW) * 4 + kB;
            uint32_t bh0, bh1, bh2, bh3, bl0, bl1, bl2, bl3;
            ldsm_x4(bh0, bh1, bh2, bh3, wHiAddr + jB);
            ldsm_x4(bl0, bl1, bl2, bl3, wLoAddr + jB);
            mma_bf16(acc[2 * jp],     ah0, ah1, ah2, ah3, bh0, bh1);
            mma_bf16(acc[2 * jp + 1], ah0, ah1, ah2, ah3, bh2, bh3);
            mma_bf16(acc[2 * jp],     al0, al1, al2, al3, bh0, bh1);
            mma_bf16(acc[2 * jp + 1], al0, al1, al2, al3, bh2, bh3);
            mma_bf16(acc[2 * jp],     ah0, ah1, ah2, ah3, bl0, bl1);
            mma_bf16(acc[2 * jp + 1], ah0, ah1, ah2, ah3, bl2, bl3);
        }
    }

    // Epilogue: scale by rsqrt(cnt+1) computed inline, store fp16 h'
    int gr0 = blockRow + rowGrp * 16 + g;
    int gr1 = gr0 + 8;
    float wn0 = (gr0 < NN) ? rsqrtf((float)(g_cnt[gr0] + 1)) : 0.f;
    float wn1 = (gr1 < NN) ? rsqrtf((float)(g_cnt[gr1] + 1)) : 0.f;
    #pragma unroll
    for (int j = 0; j < 8; j++) {
        int col = nHalf * 64 + j * 8 + 2 * t;
        if (gr0 < NN)
            *(__half2*)&outH[(size_t)gr0 * HID + col] =
                __floats2half2_rn(wn0 * acc[j][0], wn0 * acc[j][1]);
        if (gr1 < NN)
            *(__half2*)&outH[(size_t)gr1 * HID + col] =
                __floats2half2_rn(wn1 * acc[j][2], wn1 * acc[j][3]);
    }
}

// ---------------- gather-aggregate + bias + relu (+ fused output proj) -------
// agg[n] = rsqrt(cnt[n]+1) * sum_{s in N(n) U {n}} h'[s];  x = relu(agg + b)
__global__ void k_agg(int layer, const float* __restrict__ bias,
                      const float* __restrict__ Wout, const float* __restrict__ bout,
                      float* __restrict__ out) {
    const __half* h = (layer == 0 ? g_bufH1 : g_bufH2);
    __shared__ float Ws[HID * NC];
    __shared__ float bs[NC];

    int tid = threadIdx.x;
    if (Wout) {
        for (int i = tid; i < HID * NC; i += blockDim.x) Ws[i] = Wout[i];
        if (tid < NC) bs[tid] = bout[tid];
        __syncthreads();
    }

    int n = (blockIdx.x * blockDim.x + tid) >> 5;     // grid exact: 100000 warps
    int lane = tid & 31;

    float ax, ay, az, aw;
    {
        uint2 v = ((const uint2*)(h + (size_t)n * HID))[lane];
        float2 p0 = __half22float2(*(const __half2*)&v.x);
        float2 p1 = __half22float2(*(const __half2*)&v.y);
        ax = p0.x; ay = p0.y; az = p1.x; aw = p1.y;   // self term h'[n]
    }

    int beg = g_rowptr[n];
    int cnt = g_cnt[n];
    int end = beg + cnt;

    int idx = beg;
    for (; idx + 3 < end; idx += 4) {                 // 4-way MLP
        int s0 = g_col[idx];
        int s1 = g_col[idx + 1];
        int s2 = g_col[idx + 2];
        int s3 = g_col[idx + 3];
        uint2 v0 = ((const uint2*)(h + (size_t)s0 * HID))[lane];
        uint2 v1 = ((const uint2*)(h + (size_t)s1 * HID))[lane];
        uint2 v2 = ((const uint2*)(h + (size_t)s2 * HID))[lane];
        uint2 v3 = ((const uint2*)(h + (size_t)s3 * HID))[lane];
        float2 a0 = __half22float2(*(const __half2*)&v0.x);
        float2 b0 = __half22float2(*(const __half2*)&v0.y);
        float2 a1 = __half22float2(*(const __half2*)&v1.x);
        float2 b1 = __half22float2(*(const __half2*)&v1.y);
        float2 a2 = __half22float2(*(const __half2*)&v2.x);
        float2 b2 = __half22float2(*(const __half2*)&v2.y);
        float2 a3 = __half22float2(*(const __half2*)&v3.x);
        float2 b3 = __half22float2(*(const __half2*)&v3.y);
        ax += (a0.x + a1.x) + (a2.x + a3.x);
        ay += (a0.y + a1.y) + (a2.y + a3.y);
        az += (b0.x + b1.x) + (b2.x + b3.x);
        aw += (b0.y + b1.y) + (b2.y + b3.y);
    }
    for (; idx < end; idx++) {
        int s0 = g_col[idx];
        uint2 v0 = ((const uint2*)(h + (size_t)s0 * HID))[lane];
        float2 a0 = __half22float2(*(const __half2*)&v0.x);
        float2 b0 = __half22float2(*(const __half2*)&v0.y);
        ax += a0.x; ay += a0.y; az += b0.x; aw += b0.y;
    }

    float wn = rsqrtf((float)(cnt + 1));
    float4 bv = ((const float4*)bias)[lane];
    float4 r;
    r.x = fmaxf(wn * ax + bv.x, 0.f);
    r.y = fmaxf(wn * ay + bv.y, 0.f);
    r.z = fmaxf(wn * az + bv.z, 0.f);
    r.w = fmaxf(wn * aw + bv.w, 0.f);

    if (!Wout) {
        uint2 o;
        *(__half2*)&o.x = __floats2half2_rn(r.x, r.y);
        *(__half2*)&o.y = __floats2half2_rn(r.z, r.w);
        ((uint2*)(g_bufX + (size_t)n * HID))[lane] = o;
    } else {
        int kb = lane * 4;
        #pragma unroll
        for (int c = 0; c < NC; c++) {
            float s = r.x * Ws[(kb + 0) * NC + c]
                    + r.y * Ws[(kb + 1) * NC + c]
                    + r.z * Ws[(kb + 2) * NC + c]
                    + r.w * Ws[(kb + 3) * NC + c];
            #pragma unroll
            for (int off = 16; off; off >>= 1)
                s += __shfl_down_sync(0xffffffffu, s, off);
            if (lane == 0) out[(size_t)n * NC + c] = s + bs[c];
        }
    }
}

// ---------------- launch ----------------
extern "C" void kernel_launch(void* const* d_in, const int* in_sizes, int n_in,
                              void* d_out, int out_size) {
    const int*   src  = (const int*)d_in[0];          // edge_index[0]
    const int*   dst  = src + NE;                     // edge_index[1]
    const float* emb  = (const float*)d_in[1];
    const float* W1   = (const float*)d_in[2];
    const float* b1   = (const float*)d_in[3];
    const float* W2   = (const float*)d_in[4];
    const float* b2   = (const float*)d_in[5];
    const float* Wout = (const float*)d_in[6];
    const float* bout = (const float*)d_in[7];
    float* out = (float*)d_out;

    const int SCAN_BLKS  = (NN + 511) / 512;          // 196
    const int EDGE4_BLKS = (NE / 4 + 255) / 256;      // 1563
    const int GEMM_BLKS  = (NN + 127) / 128;          // 782
    const int AGG_BLKS   = (NN * 32) / 256;           // 12500

    static cudaStream_t s2 = nullptr;
    static cudaEvent_t evF = nullptr, evI = nullptr, evJ = nullptr;
    static void* cntAddr = nullptr;
    if (!s2) {
        cudaFuncSetAttribute(k_gemm_mma, cudaFuncAttributeMaxDynamicSharedMemorySize, DSMEM_SZ);
        cudaStreamCreateWithFlags(&s2, cudaStreamNonBlocking);
        cudaEventCreateWithFlags(&evF, cudaEventDisableTiming);
        cudaEventCreateWithFlags(&evI, cudaEventDisableTiming);
        cudaEventCreateWithFlags(&evJ, cudaEventDisableTiming);
        cudaGetSymbolAddress(&cntAddr, g_cnt);
    }

    // Fork: side stream starts weight images immediately (input-only deps)
    cudaEventRecord(evF, 0);
    cudaStreamWaitEvent(s2, evF, 0);
    k_wimg<<<32, 256, 0, s2>>>(W1, 0);
    k_wimg<<<32, 256, 0, s2>>>(W2, 1);

    // Main stream: counts (GEMM1's only prep dependency — epilogue rsqrt inline)
    cudaMemsetAsync(cntAddr, 0, NN * sizeof(int), 0);
    k_count<<<EDGE4_BLKS, 256>>>(dst);
    cudaEventRecord(evI, 0);

    // Side stream: GEMM1 overlaps remaining CSR build
    cudaStreamWaitEvent(s2, evI, 0);
    k_gemm_mma<<<GEMM_BLKS, 512, DSMEM_SZ, s2>>>(emb, 0, 0);
    cudaEventRecord(evJ, s2);

    // Main stream: rest of CSR build
    k_scanA<<<SCAN_BLKS, 512>>>();
    k_scanB<<<1, 256>>>(SCAN_BLKS);
    k_scanC<<<SCAN_BLKS, 512>>>();
    k_place<<<EDGE4_BLKS, 256>>>(src, dst);

    // Join, then layer-1 agg -> layer-2 GEMM -> layer-2 agg + output proj
    cudaStreamWaitEvent(0, evJ, 0);
    k_agg<<<AGG_BLKS, 256>>>(0, b1, nullptr, nullptr, nullptr);
    k_gemm_mma<<<GEMM_BLKS, 512, DSMEM_SZ>>>(nullptr, 1, 0);
    k_agg<<<AGG_BLKS, 256>>>(1, b2, Wout, bout, out);
}

// round 11
// speedup vs baseline: 1.0344x; 1.0097x over previous
#include <cuda_runtime.h>
#include <cuda_bf16.h>
#include <cuda_fp16.h>
#include <math.h>
#include <cstdint>

#define NN 100000
#define HID 128
#define NE 1600000
#define NC 10

// ---------------- scratch (device globals; no allocation allowed) -------------
__device__ int    g_cnt[NN];
__device__ int    g_rowptr[NN];
__device__ int    g_col[NE];
__device__ int    g_pos[NE];                   // intra-segment position per edge
__device__ int    g_blockSums[256];
__device__ __half g_bufH1[(size_t)NN * HID];   // layer-1 h' = invs*h (fp16)
__device__ __half g_bufH2[(size_t)NN * HID];   // layer-2 h' (fp16)
__device__ __half g_bufX[(size_t)NN * HID];    // layer-1 activation x (fp16)
// bf16 hi/lo weight images, layout [n][k/2] u32 pairs
__device__ uint32_t g_W1hi[128 * 64];
__device__ uint32_t g_W1lo[128 * 64];
__device__ uint32_t g_W2hi[128 * 64];
__device__ uint32_t g_W2lo[128 * 64];

__device__ __forceinline__ uint32_t smem_u32(const void* p) {
    uint32_t a;
    asm("{ .reg .u64 t; cvta.to.shared.u64 t, %1; cvt.u32.u64 %0, t; }" : "=r"(a) : "l"(p));
    return a;
}

// ---------------- degree histogram + position record (single atomic pass) ----
__global__ void k_count(const int* __restrict__ dst) {
    int e4 = blockIdx.x * blockDim.x + threadIdx.x;
    if (e4 < NE / 4) {
        int4 d = ((const int4*)dst)[e4];
        int4 p;
        p.x = atomicAdd(&g_cnt[d.x], 1);
        p.y = atomicAdd(&g_cnt[d.y], 1);
        p.z = atomicAdd(&g_cnt[d.z], 1);
        p.w = atomicAdd(&g_cnt[d.w], 1);
        ((int4*)g_pos)[e4] = p;
    }
}

// ---------------- exclusive scan (3-phase) ----------------
__global__ void k_scanA() {
    __shared__ int s[512];
    int i = blockIdx.x * 512 + threadIdx.x;
    int v = (i < NN) ? g_cnt[i] : 0;
    s[threadIdx.x] = v;
    __syncthreads();
    #pragma unroll
    for (int off = 1; off < 512; off <<= 1) {
        int t = (threadIdx.x >= off) ? s[threadIdx.x - off] : 0;
        __syncthreads();
        s[threadIdx.x] += t;
        __syncthreads();
    }
    if (i < NN) g_rowptr[i] = s[threadIdx.x] - v;        // exclusive
    if (threadIdx.x == 511) g_blockSums[blockIdx.x] = s[511];
}

__global__ void k_scanB(int nblocks) {
    __shared__ int s[256];
    int t = threadIdx.x;
    int v = (t < nblocks) ? g_blockSums[t] : 0;
    s[t] = v;
    __syncthreads();
    #pragma unroll
    for (int off = 1; off < 256; off <<= 1) {
        int u = (t >= off) ? s[t - off] : 0;
        __syncthreads();
        s[t] += u;
        __syncthreads();
    }
    if (t < nblocks) g_blockSums[t] = s[t] - v;           // exclusive
}

__global__ void k_scanC() {
    int i = blockIdx.x * 512 + threadIdx.x;
    if (i < NN) g_rowptr[i] += g_blockSums[blockIdx.x];
}

// ---------------- CSR place (no atomics) ----------------
__global__ void k_place(const int* __restrict__ src, const int* __restrict__ dst) {
    int e4 = blockIdx.x * blockDim.x + threadIdx.x;
    if (e4 < NE / 4) {
        int4 s = ((const int4*)src)[e4];
        int4 d = ((const int4*)dst)[e4];
        int4 p = ((const int4*)g_pos)[e4];
        g_col[g_rowptr[d.x] + p.x] = s.x;
        g_col[g_rowptr[d.y] + p.y] = s.y;
        g_col[g_rowptr[d.z] + p.z] = s.z;
        g_col[g_rowptr[d.w] + p.w] = s.w;
    }
}

// ---------------- weight image precompute ----------------
__global__ void k_wimg(const float* __restrict__ W, int layer) {
    uint32_t* hiImg = (layer == 0 ? g_W1hi : g_W2hi);
    uint32_t* loImg = (layer == 0 ? g_W1lo : g_W2lo);
    int idx = blockIdx.x * blockDim.x + threadIdx.x;      // 0..8191 (pairs)
    if (idx >= 128 * 64) return;
    int n = idx >> 6, cp = idx & 63;
    int k0 = 2 * cp;
    float w0 = W[(size_t)k0 * HID + n];
    float w1 = W[(size_t)(k0 + 1) * HID + n];
    __nv_bfloat16 h0 = __float2bfloat16(w0), h1 = __float2bfloat16(w1);
    __nv_bfloat16 l0 = __float2bfloat16(w0 - __bfloat162float(h0));
    __nv_bfloat16 l1 = __float2bfloat16(w1 - __bfloat162float(h1));
    hiImg[idx] = (uint32_t)__bfloat16_as_ushort(h0) | ((uint32_t)__bfloat16_as_ushort(h1) << 16);
    loImg[idx] = (uint32_t)__bfloat16_as_ushort(l0) | ((uint32_t)__bfloat16_as_ushort(l1) << 16);
}

// ---------------- mma.sync bf16x3 GEMM, M-tile 64, 2 CTAs/SM -----------------
// 256 threads = 8 warps: rowGrp = wid&3 (16 rows), nHalf = wid>>2 (64-col half)
// h'[r][:] = rsqrt(cnt[r]+1) * (A[r][:] @ W), stored fp16.
#define ROWW 68
#define MAT_A (64 * ROWW)                  // 4352 words
#define OFF_WHI (2 * MAT_A)                // 8704 words
#define OFF_WLO (OFF_WHI + 128 * ROWW)     // 17408 words
#define DSMEM_SZ ((OFF_WLO + 128 * ROWW) * 4)   // 104448 bytes

__device__ __forceinline__ void mma_bf16(float* d, uint32_t a0, uint32_t a1,
                                         uint32_t a2, uint32_t a3,
                                         uint32_t b0, uint32_t b1) {
    asm volatile(
        "mma.sync.aligned.m16n8k16.row.col.f32.bf16.bf16.f32 "
        "{%0,%1,%2,%3}, {%4,%5,%6,%7}, {%8,%9}, {%0,%1,%2,%3};\n"
        : "+f"(d[0]), "+f"(d[1]), "+f"(d[2]), "+f"(d[3])
        : "r"(a0), "r"(a1), "r"(a2), "r"(a3), "r"(b0), "r"(b1));
}

__device__ __forceinline__ void ldsm_x4(uint32_t& r0, uint32_t& r1, uint32_t& r2,
                                        uint32_t& r3, uint32_t addr) {
    asm volatile("ldmatrix.sync.aligned.m8n8.x4.shared.b16 {%0,%1,%2,%3}, [%4];"
                 : "=r"(r0), "=r"(r1), "=r"(r2), "=r"(r3) : "r"(addr));
}

__global__ void __launch_bounds__(256, 2) k_gemm_mma(const float* Af32, int layer, int rowBase) {
    extern __shared__ uint32_t sm[];
    uint32_t* sAhi = sm;
    uint32_t* sAlo = sm + MAT_A;
    uint32_t* sWhi = sm + OFF_WHI;
    uint32_t* sWlo = sm + OFF_WLO;

    const uint32_t* whi = (layer == 0 ? g_W1hi : g_W2hi);
    const uint32_t* wlo = (layer == 0 ? g_W1lo : g_W2lo);
    __half* outH = (layer == 0 ? g_bufH1 : g_bufH2);

    int tid = threadIdx.x;
    int wid = tid >> 5, lane = tid & 31;
    int g = lane >> 2, t = lane & 3;
    int rowGrp = wid & 3;                     // which 16-row stripe of 64
    int nHalf = wid >> 2;                     // which 64-col half
    int blockRow = rowBase + blockIdx.x * 64;

    // Stage W images (128 x 64 words each)
    #pragma unroll
    for (int i = 0; i < 32; i++) {
        int idx = tid + i * 256;
        int row = idx >> 6, c = idx & 63;
        sWhi[row * ROWW + c] = whi[idx];
        sWlo[row * ROWW + c] = wlo[idx];
    }

    // Convert A tile (64 rows; fp32 input or fp16 g_bufX) -> bf16 hi/lo
    #pragma unroll
    for (int i = 0; i < 16; i++) {
        int idx = tid + i * 256;              // 0..4095 pairs
        int row = idx >> 6, c = idx & 63;
        int gr = blockRow + row;
        float2 v = make_float2(0.f, 0.f);
        if (gr < NN) {
            if (Af32) {
                v = *(const float2*)&Af32[(size_t)gr * HID + 2 * c];
            } else {
                uint32_t u = ((const uint32_t*)(g_bufX + (size_t)gr * HID))[c];
                v = __half22float2(*(const __half2*)&u);
            }
        }
        __nv_bfloat16 h0 = __float2bfloat16(v.x), h1 = __float2bfloat16(v.y);
        __nv_bfloat16 l0 = __float2bfloat16(v.x - __bfloat162float(h0));
        __nv_bfloat16 l1 = __float2bfloat16(v.y - __bfloat162float(h1));
        sAhi[row * ROWW + c] = (uint32_t)__bfloat16_as_ushort(h0) | ((uint32_t)__bfloat16_as_ushort(h1) << 16);
        sAlo[row * ROWW + c] = (uint32_t)__bfloat16_as_ushort(l0) | ((uint32_t)__bfloat16_as_ushort(l1) << 16);
    }
    __syncthreads();

    float acc[8][4];
    #pragma unroll
    for (int j = 0; j < 8; j++)
        #pragma unroll
        for (int q = 0; q < 4; q++) acc[j][q] = 0.f;

    // ldmatrix per-lane base addresses
    int grp = lane >> 3, l8 = lane & 7;
    uint32_t base = smem_u32(sm);
    // A x4: grp0 -> m0-7/k0, grp1 -> m8-15/k0, grp2 -> m0-7/k+8, grp3 -> m8-15/k+8
    uint32_t aOff = (uint32_t)((rowGrp * 16 + (grp & 1) * 8 + l8) * ROWW + (grp >> 1) * 4) * 4;
    uint32_t aHiAddr = base + aOff;
    uint32_t aLoAddr = base + MAT_A * 4 + aOff;
    // W x4 (j-pair): grp0 -> +0/k0, grp1 -> +0/k+8, grp2 -> +8/k0, grp3 -> +8/k+8
    uint32_t wOff = (uint32_t)((nHalf * 64 + (grp >> 1) * 8 + l8) * ROWW + (grp & 1) * 4) * 4;
    uint32_t wHiAddr = base + OFF_WHI * 4 + wOff;
    uint32_t wLoAddr = base + OFF_WLO * 4 + wOff;

    #pragma unroll
    for (int kc = 0; kc < 8; kc++) {
        uint32_t kB = kc * 32;                // 8 words per k-chunk
        uint32_t ah0, ah1, ah2, ah3, al0, al1, al2, al3;
        ldsm_x4(ah0, ah1, ah2, ah3, aHiAddr + kB);
        ldsm_x4(al0, al1, al2, al3, aLoAddr + kB);
        #pragma unroll
        for (int jp = 0; jp < 4; jp++) {
            uint32_t jB = (uint32_t)(jp * 16 * ROWW) * 4 + kB;
            uint32_t bh0, bh1, bh2, bh3, bl0, bl1, bl2, bl3;
            ldsm_x4(bh0, bh1, bh2, bh3, wHiAddr + jB);
            ldsm_x4(bl0, bl1, bl2, bl3, wLoAddr + jB);
            mma_bf16(acc[2 * jp],     ah0, ah1, ah2, ah3, bh0, bh1);
            mma_bf16(acc[2 * jp + 1], ah0, ah1, ah2, ah3, bh2, bh3);
            mma_bf16(acc[2 * jp],     al0, al1, al2, al3, bh0, bh1);
            mma_bf16(acc[2 * jp + 1], al0, al1, al2, al3, bh2, bh3);
            mma_bf16(acc[2 * jp],     ah0, ah1, ah2, ah3, bl0, bl1);
            mma_bf16(acc[2 * jp + 1], ah0, ah1, ah2, ah3, bl2, bl3);
        }
    }

    // Epilogue: scale by rsqrt(cnt+1) computed inline, store fp16 h'
    int gr0 = blockRow + rowGrp * 16 + g;
    int gr1 = gr0 + 8;
    float wn0 = (gr0 < NN) ? rsqrtf((float)(g_cnt[gr0] + 1)) : 0.f;
    float wn1 = (gr1 < NN) ? rsqrtf((float)(g_cnt[gr1] + 1)) : 0.f;
    #pragma unroll
    for (int j = 0; j < 8; j++) {
        int col = nHalf * 64 + j * 8 + 2 * t;
        if (gr0 < NN)
            *(__half2*)&outH[(size_t)gr0 * HID + col] =
                __floats2half2_rn(wn0 * acc[j][0], wn0 * acc[j][1]);
        if (gr1 < NN)
            *(__half2*)&outH[(size_t)gr1 * HID + col] =
                __floats2half2_rn(wn1 * acc[j][2], wn1 * acc[j][3]);
    }
}

// ---------------- gather-aggregate + bias + relu (+ fused output proj) -------
// agg[n] = rsqrt(cnt[n]+1) * sum_{s in N(n) U {n}} h'[s];  x = relu(agg + b)
__global__ void k_agg(int layer, const float* __restrict__ bias,
                      const float* __restrict__ Wout, const float* __restrict__ bout,
                      float* __restrict__ out) {
    const __half* h = (layer == 0 ? g_bufH1 : g_bufH2);
    __shared__ float Ws[HID * NC];
    __shared__ float bs[NC];

    int tid = threadIdx.x;
    if (Wout) {
        for (int i = tid; i < HID * NC; i += blockDim.x) Ws[i] = Wout[i];
        if (tid < NC) bs[tid] = bout[tid];
        __syncthreads();
    }

    int n = (blockIdx.x * blockDim.x + tid) >> 5;     // grid exact: 100000 warps
    int lane = tid & 31;

    float ax, ay, az, aw;
    {
        uint2 v = ((const uint2*)(h + (size_t)n * HID))[lane];
        float2 p0 = __half22float2(*(const __half2*)&v.x);
        float2 p1 = __half22float2(*(const __half2*)&v.y);
        ax = p0.x; ay = p0.y; az = p1.x; aw = p1.y;   // self term h'[n]
    }

    int beg = g_rowptr[n];
    int cnt = g_cnt[n];
    int end = beg + cnt;

    int idx = beg;
    for (; idx + 3 < end; idx += 4) {                 // 4-way MLP
        int s0 = g_col[idx];
        int s1 = g_col[idx + 1];
        int s2 = g_col[idx + 2];
        int s3 = g_col[idx + 3];
        uint2 v0 = ((const uint2*)(h + (size_t)s0 * HID))[lane];
        uint2 v1 = ((const uint2*)(h + (size_t)s1 * HID))[lane];
        uint2 v2 = ((const uint2*)(h + (size_t)s2 * HID))[lane];
        uint2 v3 = ((const uint2*)(h + (size_t)s3 * HID))[lane];
        float2 a0 = __half22float2(*(const __half2*)&v0.x);
        float2 b0 = __half22float2(*(const __half2*)&v0.y);
        float2 a1 = __half22float2(*(const __half2*)&v1.x);
        float2 b1 = __half22float2(*(const __half2*)&v1.y);
        float2 a2 = __half22float2(*(const __half2*)&v2.x);
        float2 b2 = __half22float2(*(const __half2*)&v2.y);
        float2 a3 = __half22float2(*(const __half2*)&v3.x);
        float2 b3 = __half22float2(*(const __half2*)&v3.y);
        ax += (a0.x + a1.x) + (a2.x + a3.x);
        ay += (a0.y + a1.y) + (a2.y + a3.y);
        az += (b0.x + b1.x) + (b2.x + b3.x);
        aw += (b0.y + b1.y) + (b2.y + b3.y);
    }
    for (; idx < end; idx++) {
        int s0 = g_col[idx];
        uint2 v0 = ((const uint2*)(h + (size_t)s0 * HID))[lane];
        float2 a0 = __half22float2(*(const __half2*)&v0.x);
        float2 b0 = __half22float2(*(const __half2*)&v0.y);
        ax += a0.x; ay += a0.y; az += b0.x; aw += b0.y;
    }

    float wn = rsqrtf((float)(cnt + 1));
    float4 bv = ((const float4*)bias)[lane];
    float4 r;
    r.x = fmaxf(wn * ax + bv.x, 0.f);
    r.y = fmaxf(wn * ay + bv.y, 0.f);
    r.z = fmaxf(wn * az + bv.z, 0.f);
    r.w = fmaxf(wn * aw + bv.w, 0.f);

    if (!Wout) {
        uint2 o;
        *(__half2*)&o.x = __floats2half2_rn(r.x, r.y);
        *(__half2*)&o.y = __floats2half2_rn(r.z, r.w);
        ((uint2*)(g_bufX + (size_t)n * HID))[lane] = o;
    } else {
        int kb = lane * 4;
        #pragma unroll
        for (int c = 0; c < NC; c++) {
            float s = r.x * Ws[(kb + 0) * NC + c]
                    + r.y * Ws[(kb + 1) * NC + c]
                    + r.z * Ws[(kb + 2) * NC + c]
                    + r.w * Ws[(kb + 3) * NC + c];
            #pragma unroll
            for (int off = 16; off; off >>= 1)
                s += __shfl_down_sync(0xffffffffu, s, off);
            if (lane == 0) out[(size_t)n * NC + c] = s + bs[c];
        }
    }
}

// ---------------- launch ----------------
extern "C" void kernel_launch(void* const* d_in, const int* in_sizes, int n_in,
                              void* d_out, int out_size) {
    const int*   src  = (const int*)d_in[0];          // edge_index[0]
    const int*   dst  = src + NE;                     // edge_index[1]
    const float* emb  = (const float*)d_in[1];
    const float* W1   = (const float*)d_in[2];
    const float* b1   = (const float*)d_in[3];
    const float* W2   = (const float*)d_in[4];
    const float* b2   = (const float*)d_in[5];
    const float* Wout = (const float*)d_in[6];
    const float* bout = (const float*)d_in[7];
    float* out = (float*)d_out;

    const int SCAN_BLKS  = (NN + 511) / 512;          // 196
    const int EDGE4_BLKS = (NE / 4 + 255) / 256;      // 1563
    const int GEMM_BLKS  = (NN + 63) / 64;            // 1563 (M-tile 64)
    const int AGG_BLKS   = (NN * 32) / 256;           // 12500

    static cudaStream_t s2 = nullptr;
    static cudaEvent_t evF = nullptr, evI = nullptr, evJ = nullptr;
    static void* cntAddr = nullptr;
    if (!s2) {
        cudaFuncSetAttribute(k_gemm_mma, cudaFuncAttributeMaxDynamicSharedMemorySize, DSMEM_SZ);
        cudaStreamCreateWithFlags(&s2, cudaStreamNonBlocking);
        cudaEventCreateWithFlags(&evF, cudaEventDisableTiming);
        cudaEventCreateWithFlags(&evI, cudaEventDisableTiming);
        cudaEventCreateWithFlags(&evJ, cudaEventDisableTiming);
        cudaGetSymbolAddress(&cntAddr, g_cnt);
    }

    // Fork: side stream starts weight images immediately (input-only deps)
    cudaEventRecord(evF, 0);
    cudaStreamWaitEvent(s2, evF, 0);
    k_wimg<<<32, 256, 0, s2>>>(W1, 0);
    k_wimg<<<32, 256, 0, s2>>>(W2, 1);

    // Main stream: counts (GEMM1's only prep dependency — epilogue rsqrt inline)
    cudaMemsetAsync(cntAddr, 0, NN * sizeof(int), 0);
    k_count<<<EDGE4_BLKS, 256>>>(dst);
    cudaEventRecord(evI, 0);

    // Side stream: GEMM1 overlaps remaining CSR build
    cudaStreamWaitEvent(s2, evI, 0);
    k_gemm_mma<<<GEMM_BLKS, 256, DSMEM_SZ, s2>>>(emb, 0, 0);
    cudaEventRecord(evJ, s2);

    // Main stream: rest of CSR build
    k_scanA<<<SCAN_BLKS, 512>>>();
    k_scanB<<<1, 256>>>(SCAN_BLKS);
    k_scanC<<<SCAN_BLKS, 512>>>();
    k_place<<<EDGE4_BLKS, 256>>>(src, dst);

    // Join, then layer-1 agg -> layer-2 GEMM -> layer-2 agg + output proj
    cudaStreamWaitEvent(0, evJ, 0);
    k_agg<<<AGG_BLKS, 256>>>(0, b1, nullptr, nullptr, nullptr);
    k_gemm_mma<<<GEMM_BLKS, 256, DSMEM_SZ>>>(nullptr, 1, 0);
    k_agg<<<AGG_BLKS, 256>>>(1, b2, Wout, bout, out);
}